// round 13
// baseline (speedup 1.0000x reference)
#include <cuda_runtime.h>
#include <cuda_fp16.h>
#include <stdint.h>
#include <math.h>

#define N_NODES 100000
#define E_EDGES 3200000
#define C_IN 256
#define C1 64
#define C2 40
#define SCAN_B 1024
#define NBLK ((N_NODES + SCAN_B - 1) / SCAN_B)   // 98

// ---------------- scratch (device globals; allocation-free) ----------------
__device__ __align__(16) float g_dinv[N_NODES];
__device__ __align__(16) int   g_degi[N_NODES];
__device__ __align__(16) int   g_row[N_NODES];
__device__ __align__(16) int   g_rowtmp[N_NODES];
__device__ __align__(16) int   g_cur[N_NODES];
__device__ __align__(16) int   g_bsum[NBLK];
__device__ __align__(16) int2  g_edge[E_EDGES];          // CSR: {src, norm bits}
__device__ __align__(16) __half2 g_xw1h[(N_NODES + 128) * 32];  // x@W1, half2
__device__ __align__(16) float g_out1[N_NODES * C1];     // relu'd aggregate
__device__ __align__(16) __half2 g_xw2h[N_NODES * 20 + 64];  // out1@W2, half2
__device__ int g_is64;

// ---------------- zero + dtype detection ------------------------------------
__global__ void k_zero_detect(const int* __restrict__ ei32) {
    int i = blockIdx.x * blockDim.x + threadIdx.x;
    if (i < N_NODES) g_degi[i] = 0;
    if (i == 0) {
        int all0 = 1;
        for (int k = 0; k < 64; k++)
            if (ei32[2 * k + 1] != 0) { all0 = 0; break; }
        g_is64 = all0;
    }
}

// ---------------- CSR build (4 edges per thread) ----------------
__global__ void k_deg_count(const int* __restrict__ ei32) {
    int e4 = blockIdx.x * blockDim.x + threadIdx.x;
    int e = e4 * 4;
    if (e >= E_EDGES) return;
    if (!g_is64) {
        int4 d = *(const int4*)(ei32 + E_EDGES + e);
        atomicAdd(&g_degi[d.x], 1);
        atomicAdd(&g_degi[d.y], 1);
        atomicAdd(&g_degi[d.z], 1);
        atomicAdd(&g_degi[d.w], 1);
    } else {
#pragma unroll
        for (int i = 0; i < 4; i++)
            atomicAdd(&g_degi[ei32[2 * (E_EDGES + e + i)]], 1);
    }
}

__global__ void k_scan1_dinv() {
    __shared__ int sh[SCAN_B];
    int i = blockIdx.x * SCAN_B + threadIdx.x;
    int v = (i < N_NODES) ? g_degi[i] : 0;
    if (i < N_NODES) g_dinv[i] = rsqrtf((float)(v + 1));     // +1 self loop
    sh[threadIdx.x] = v;
    __syncthreads();
    for (int off = 1; off < SCAN_B; off <<= 1) {
        int t = (threadIdx.x >= off) ? sh[threadIdx.x - off] : 0;
        __syncthreads();
        sh[threadIdx.x] += t;
        __syncthreads();
    }
    if (i < N_NODES) g_rowtmp[i] = sh[threadIdx.x];
    if (threadIdx.x == SCAN_B - 1) g_bsum[blockIdx.x] = sh[SCAN_B - 1];
}

// scan2+scan3 merged: each block (256 nodes) lies inside ONE 1024-node scan
// block, so it needs a single boff = sum of g_bsum[0 .. (bid>>2)-1].
__global__ void k_scan23() {
    __shared__ int sh[256];
    int t = threadIdx.x;
    int myblk = blockIdx.x >> 2;             // which SCAN_B block we're in
    sh[t] = (t < myblk) ? g_bsum[t] : 0;     // myblk <= 97 < 256
    __syncthreads();
#pragma unroll
    for (int off = 128; off > 0; off >>= 1) {
        if (t < off) sh[t] += sh[t + off];
        __syncthreads();
    }
    int boff = sh[0];
    int i = blockIdx.x * 256 + t;
    if (i < N_NODES) {
        int r = g_rowtmp[i] - g_degi[i] + boff;
        g_row[i] = r;
        g_cur[i] = r;
    }
}

__global__ void k_fill(const int* __restrict__ ei32) {
    int e4 = blockIdx.x * blockDim.x + threadIdx.x;
    int e = e4 * 4;
    if (e >= E_EDGES) return;
    int s[4], d[4];
    if (!g_is64) {
        int4 sv = *(const int4*)(ei32 + e);
        int4 dv = *(const int4*)(ei32 + E_EDGES + e);
        s[0] = sv.x; s[1] = sv.y; s[2] = sv.z; s[3] = sv.w;
        d[0] = dv.x; d[1] = dv.y; d[2] = dv.z; d[3] = dv.w;
    } else {
#pragma unroll
        for (int i = 0; i < 4; i++) {
            s[i] = ei32[2 * (e + i)];
            d[i] = ei32[2 * (E_EDGES + e + i)];
        }
    }
#pragma unroll
    for (int i = 0; i < 4; i++) {
        int pos = atomicAdd(&g_cur[d[i]], 1);
        float nrm = g_dinv[s[i]] * g_dinv[d[i]];
        g_edge[pos] = make_int2(s[i], __float_as_int(nrm));
    }
}

// ---------------- GEMM1: xw1 = x @ W1 via tf32 mma.sync, half2 epilogue ----
__device__ __forceinline__ uint32_t f2tf32(float f) {
    uint32_t u;
    asm("cvt.rna.tf32.f32 %0, %1;" : "=r"(u) : "f"(f));
    return u;
}

__device__ __forceinline__ void mma_tf32(float* c, const uint32_t* a,
                                         uint32_t b0, uint32_t b1) {
    asm volatile(
        "mma.sync.aligned.m16n8k8.row.col.f32.tf32.tf32.f32 "
        "{%0,%1,%2,%3}, {%4,%5,%6,%7}, {%8,%9}, {%0,%1,%2,%3};"
        : "+f"(c[0]), "+f"(c[1]), "+f"(c[2]), "+f"(c[3])
        : "r"(a[0]), "r"(a[1]), "r"(a[2]), "r"(a[3]), "r"(b0), "r"(b1));
}

#define G1_KT 32

__global__ void k_gemm1(const float* __restrict__ x, const float* __restrict__ W1) {
    __shared__ uint32_t xs[128][36];
    __shared__ uint32_t ws[G1_KT][68];
    int tid = threadIdx.x;
    int wid = tid >> 5;
    int lane = tid & 31;
    int g = lane >> 2;
    int tcol = lane & 3;
    int rb = blockIdx.x * 128;
    int R = wid * 16;

    float c[8][4];
#pragma unroll
    for (int j = 0; j < 8; j++)
#pragma unroll
        for (int i = 0; i < 4; i++) c[j][i] = 0.0f;

    for (int kc = 0; kc < C_IN; kc += G1_KT) {
#pragma unroll
        for (int it = 0; it < 4; it++) {
            int i = tid + 256 * it;
            int row = i >> 3;
            int k4 = (i & 7) << 2;
            int grow = rb + row;
            float4 v = make_float4(0.f, 0.f, 0.f, 0.f);
            if (grow < N_NODES)
                v = *(const float4*)(x + (long)grow * C_IN + kc + k4);
            xs[row][k4 + 0] = f2tf32(v.x);
            xs[row][k4 + 1] = f2tf32(v.y);
            xs[row][k4 + 2] = f2tf32(v.z);
            xs[row][k4 + 3] = f2tf32(v.w);
        }
#pragma unroll
        for (int it = 0; it < 2; it++) {
            int i = tid + 256 * it;
            int wk = i >> 4;
            int wc = (i & 15) << 2;
            float4 v = *(const float4*)(W1 + (kc + wk) * C1 + wc);
            ws[wk][wc + 0] = f2tf32(v.x);
            ws[wk][wc + 1] = f2tf32(v.y);
            ws[wk][wc + 2] = f2tf32(v.z);
            ws[wk][wc + 3] = f2tf32(v.w);
        }
        __syncthreads();

#pragma unroll
        for (int kk = 0; kk < 4; kk++) {
            uint32_t a[4];
            a[0] = xs[R + g][kk * 8 + tcol];
            a[1] = xs[R + g + 8][kk * 8 + tcol];
            a[2] = xs[R + g][kk * 8 + tcol + 4];
            a[3] = xs[R + g + 8][kk * 8 + tcol + 4];
#pragma unroll
            for (int j = 0; j < 8; j++) {
                uint32_t b0 = ws[kk * 8 + tcol][j * 8 + g];
                uint32_t b1 = ws[kk * 8 + tcol + 4][j * 8 + g];
                mma_tf32(c[j], a, b0, b1);
            }
        }
        __syncthreads();
    }

    int row0 = rb + R + g;
    int row1 = row0 + 8;
#pragma unroll
    for (int j = 0; j < 8; j++) {
        int h2col = (j * 8 + 2 * tcol) >> 1;
        if (row0 < N_NODES)
            g_xw1h[(long)row0 * 32 + h2col] = __floats2half2_rn(c[j][0], c[j][1]);
        if (row1 < N_NODES)
            g_xw1h[(long)row1 * 32 + h2col] = __floats2half2_rn(c[j][2], c[j][3]);
    }
}

// --------- layer-1 aggregation (+relu): warp per node, pipelined gather ----
__global__ void k_agg1(const float* __restrict__ b1) {
    int w = (blockIdx.x * blockDim.x + threadIdx.x) >> 5;
    int lane = threadIdx.x & 31;
    if (w >= N_NODES) return;
    float dv = g_dinv[w];
    float sl = dv * dv;
    float2 xv = __half22float2(g_xw1h[(long)w * 32 + lane]);
    float2 bv = *(const float2*)(b1 + 2 * lane);
    float a0 = xv.x * sl + bv.x;
    float a1 = xv.y * sl + bv.y;
    int j = g_row[w];
    int end = j + g_degi[w];

    int2 e[8];
    if (j + 8 <= end) {
#pragma unroll
        for (int i = 0; i < 8; i++) e[i] = g_edge[j + i];
    }
    while (j + 8 <= end) {
        // gathers for current batch
        float2 v[8];
#pragma unroll
        for (int i = 0; i < 8; i++)
            v[i] = __half22float2(g_xw1h[(long)e[i].x * 32 + lane]);
        // prefetch next batch's edge records while gathers are in flight
        int jn = j + 8;
        int2 en[8];
        if (jn + 8 <= end) {
#pragma unroll
            for (int i = 0; i < 8; i++) en[i] = g_edge[jn + i];
        }
#pragma unroll
        for (int i = 0; i < 8; i++) {
            float n = __int_as_float(e[i].y);
            a0 += v[i].x * n;
            a1 += v[i].y * n;
        }
#pragma unroll
        for (int i = 0; i < 8; i++) e[i] = en[i];
        j = jn;
    }
    for (; j < end; j++) {
        int2 ee = g_edge[j];
        float n = __int_as_float(ee.y);
        float2 v = __half22float2(g_xw1h[(long)ee.x * 32 + lane]);
        a0 += v.x * n;
        a1 += v.y * n;
    }
    float2 o;
    o.x = fmaxf(a0, 0.0f);
    o.y = fmaxf(a1, 0.0f);
    *(float2*)(g_out1 + (long)w * C1 + 2 * lane) = o;
}

// ------- GEMM2: xw2 = out1 @ W2 (out1 already relu'd), half2 output --------
__global__ void k_gemm2(const float* __restrict__ W2) {
    __shared__ float xs[64][68];
    __shared__ float ws[64 * 40];
    int t = threadIdx.x;
    int rb = blockIdx.x * 64;
    int r = t >> 2, q = t & 3;

    for (int i = t; i < 64 * 40; i += 256) ws[i] = W2[i];
#pragma unroll
    for (int it = 0; it < 4; it++) {
        int i = t + 256 * it;
        int rr = i >> 4, cc = (i & 15) << 2;
        int row = rb + rr;
        float4 v = make_float4(0.f, 0.f, 0.f, 0.f);
        if (row < N_NODES)
            v = *(const float4*)(g_out1 + (long)row * C1 + cc);
        *(float4*)(&xs[rr][cc]) = v;
    }
    __syncthreads();

    float acc[10];
#pragma unroll
    for (int j = 0; j < 10; j++) acc[j] = 0.0f;
#pragma unroll
    for (int k = 0; k < 64; k++) {
        float xv = xs[r][k];
#pragma unroll
        for (int j = 0; j < 10; j++)
            acc[j] += xv * ws[k * 40 + q * 10 + j];
    }
    int row = rb + r;
    if (row < N_NODES) {
        __half2* o = g_xw2h + (long)row * 20 + q * 5;
#pragma unroll
        for (int j = 0; j < 5; j++)
            o[j] = __floats2half2_rn(acc[2 * j], acc[2 * j + 1]);
    }
}

// ---- layer-2 aggregation + fused log_softmax: warp per node, pipelined ----
__global__ void k_agg2_lsm(const float* __restrict__ b2, float* __restrict__ out) {
    int w = (blockIdx.x * blockDim.x + threadIdx.x) >> 5;
    int lane = threadIdx.x & 31;
    if (w >= N_NODES) return;
    bool act = (lane < 20);
    float dv = g_dinv[w];
    float sl = dv * dv;
    float a0 = 0.0f, a1 = 0.0f;
    if (act) {
        float2 xv = __half22float2(g_xw2h[(long)w * 20 + lane]);
        float2 bv = *(const float2*)(b2 + 2 * lane);
        a0 = xv.x * sl + bv.x;
        a1 = xv.y * sl + bv.y;
    }
    int j = g_row[w];
    int end = j + g_degi[w];

    int2 e[8];
    if (j + 8 <= end) {
#pragma unroll
        for (int i = 0; i < 8; i++) e[i] = g_edge[j + i];
    }
    while (j + 8 <= end) {
        float2 v[8];
        if (act) {
#pragma unroll
            for (int i = 0; i < 8; i++)
                v[i] = __half22float2(g_xw2h[(long)e[i].x * 20 + lane]);
        }
        int jn = j + 8;
        int2 en[8];
        if (jn + 8 <= end) {
#pragma unroll
            for (int i = 0; i < 8; i++) en[i] = g_edge[jn + i];
        }
        if (act) {
#pragma unroll
            for (int i = 0; i < 8; i++) {
                float n = __int_as_float(e[i].y);
                a0 += v[i].x * n;
                a1 += v[i].y * n;
            }
        }
#pragma unroll
        for (int i = 0; i < 8; i++) e[i] = en[i];
        j = jn;
    }
    for (; j < end; j++) {
        int2 ee = g_edge[j];
        if (act) {
            float n = __int_as_float(ee.y);
            float2 v = __half22float2(g_xw2h[(long)ee.x * 20 + lane]);
            a0 += v.x * n;
            a1 += v.y * n;
        }
    }

    float m = act ? fmaxf(a0, a1) : -INFINITY;
#pragma unroll
    for (int off = 16; off > 0; off >>= 1)
        m = fmaxf(m, __shfl_xor_sync(0xFFFFFFFFu, m, off));
    float s = act ? (expf(a0 - m) + expf(a1 - m)) : 0.0f;
#pragma unroll
    for (int off = 16; off > 0; off >>= 1)
        s += __shfl_xor_sync(0xFFFFFFFFu, s, off);
    float lse = m + logf(s);
    if (act) {
        float2 o = make_float2(a0 - lse, a1 - lse);
        *(float2*)(out + (long)w * C2 + 2 * lane) = o;
    }
}

// ---------------- launch: fork CSR build alongside GEMM1 --------------------
extern "C" void kernel_launch(void* const* d_in, const int* in_sizes, int n_in,
                              void* d_out, int out_size) {
    const float* x   = (const float*)d_in[0];
    const int*   ei  = (const int*)d_in[1];
    const float* W1  = (const float*)d_in[2];
    const float* b1  = (const float*)d_in[3];
    const float* W2  = (const float*)d_in[4];
    const float* b2  = (const float*)d_in[5];
    float* out = (float*)d_out;

    const int TB = 256;

    static cudaStream_t s_csr = nullptr;
    static cudaEvent_t ev_fork = nullptr, ev_join = nullptr;
    if (s_csr == nullptr) {
        cudaStreamCreateWithFlags(&s_csr, cudaStreamNonBlocking);
        cudaEventCreateWithFlags(&ev_fork, cudaEventDisableTiming);
        cudaEventCreateWithFlags(&ev_join, cudaEventDisableTiming);
    }

    cudaEventRecord(ev_fork, 0);
    cudaStreamWaitEvent(s_csr, ev_fork, 0);

    k_zero_detect<<<(N_NODES + TB - 1) / TB, TB, 0, s_csr>>>(ei);
    k_deg_count<<<(E_EDGES / 4 + TB - 1) / TB, TB, 0, s_csr>>>(ei);
    k_scan1_dinv<<<NBLK, SCAN_B, 0, s_csr>>>();
    k_scan23<<<(N_NODES + 255) / 256, 256, 0, s_csr>>>();
    k_fill<<<(E_EDGES / 4 + TB - 1) / TB, TB, 0, s_csr>>>(ei);
    cudaEventRecord(ev_join, s_csr);

    k_gemm1<<<(N_NODES + 127) / 128, 256>>>(x, W1);

    cudaStreamWaitEvent(0, ev_join, 0);

    k_agg1<<<(N_NODES * 32 + TB - 1) / TB, TB>>>(b1);
    k_gemm2<<<(N_NODES + 63) / 64, 256>>>(W2);
    k_agg2_lsm<<<(N_NODES * 32 + TB - 1) / TB, TB>>>(b2, out);
}

// round 14
// speedup vs baseline: 1.1331x; 1.1331x over previous
#include <cuda_runtime.h>
#include <cuda_fp16.h>
#include <stdint.h>
#include <math.h>

#define N_NODES 100000
#define E_EDGES 3200000
#define C_IN 256
#define C1 64
#define C2 40
#define SCAN_B 1024
#define NBLK ((N_NODES + SCAN_B - 1) / SCAN_B)   // 98

// ---------------- scratch (device globals; allocation-free) ----------------
__device__ __align__(16) float g_dinv[N_NODES];
__device__ __align__(16) int   g_degi[N_NODES];
__device__ __align__(16) int   g_row[N_NODES];
__device__ __align__(16) int   g_rowtmp[N_NODES];
__device__ __align__(16) int   g_cur[N_NODES];
__device__ __align__(16) int   g_bsum[NBLK];
__device__ __align__(16) int2  g_edge[E_EDGES];          // CSR: {src, norm bits}
__device__ __align__(16) __half2 g_xw1h[(N_NODES + 128) * 32];  // x@W1, half2
__device__ __align__(16) float g_out1[N_NODES * C1];     // relu'd aggregate
__device__ __align__(16) __half2 g_xw2h[N_NODES * 20 + 64];  // out1@W2, half2
__device__ int g_is64;

// ---------------- zero + dtype detection ------------------------------------
__global__ void k_zero_detect(const int* __restrict__ ei32) {
    int i = blockIdx.x * blockDim.x + threadIdx.x;
    if (i < N_NODES) g_degi[i] = 0;
    if (i == 0) {
        int all0 = 1;
        for (int k = 0; k < 64; k++)
            if (ei32[2 * k + 1] != 0) { all0 = 0; break; }
        g_is64 = all0;
    }
}

// ---------------- CSR build (4 edges per thread) ----------------
__global__ void k_deg_count(const int* __restrict__ ei32) {
    int e4 = blockIdx.x * blockDim.x + threadIdx.x;
    int e = e4 * 4;
    if (e >= E_EDGES) return;
    if (!g_is64) {
        int4 d = *(const int4*)(ei32 + E_EDGES + e);
        atomicAdd(&g_degi[d.x], 1);
        atomicAdd(&g_degi[d.y], 1);
        atomicAdd(&g_degi[d.z], 1);
        atomicAdd(&g_degi[d.w], 1);
    } else {
#pragma unroll
        for (int i = 0; i < 4; i++)
            atomicAdd(&g_degi[ei32[2 * (E_EDGES + e + i)]], 1);
    }
}

__global__ void k_scan1_dinv() {
    __shared__ int sh[SCAN_B];
    int i = blockIdx.x * SCAN_B + threadIdx.x;
    int v = (i < N_NODES) ? g_degi[i] : 0;
    if (i < N_NODES) g_dinv[i] = rsqrtf((float)(v + 1));     // +1 self loop
    sh[threadIdx.x] = v;
    __syncthreads();
    for (int off = 1; off < SCAN_B; off <<= 1) {
        int t = (threadIdx.x >= off) ? sh[threadIdx.x - off] : 0;
        __syncthreads();
        sh[threadIdx.x] += t;
        __syncthreads();
    }
    if (i < N_NODES) g_rowtmp[i] = sh[threadIdx.x];
    if (threadIdx.x == SCAN_B - 1) g_bsum[blockIdx.x] = sh[SCAN_B - 1];
}

// scan2+scan3 merged: each block (256 nodes) lies inside ONE 1024-node scan
// block, so it needs a single boff = sum of g_bsum[0 .. (bid>>2)-1].
__global__ void k_scan23() {
    __shared__ int sh[256];
    int t = threadIdx.x;
    int myblk = blockIdx.x >> 2;             // which SCAN_B block we're in
    sh[t] = (t < myblk) ? g_bsum[t] : 0;     // myblk <= 97 < 256
    __syncthreads();
#pragma unroll
    for (int off = 128; off > 0; off >>= 1) {
        if (t < off) sh[t] += sh[t + off];
        __syncthreads();
    }
    int boff = sh[0];
    int i = blockIdx.x * 256 + t;
    if (i < N_NODES) {
        int r = g_rowtmp[i] - g_degi[i] + boff;
        g_row[i] = r;
        g_cur[i] = r;
    }
}

__global__ void k_fill(const int* __restrict__ ei32) {
    int e4 = blockIdx.x * blockDim.x + threadIdx.x;
    int e = e4 * 4;
    if (e >= E_EDGES) return;
    int s[4], d[4];
    if (!g_is64) {
        int4 sv = *(const int4*)(ei32 + e);
        int4 dv = *(const int4*)(ei32 + E_EDGES + e);
        s[0] = sv.x; s[1] = sv.y; s[2] = sv.z; s[3] = sv.w;
        d[0] = dv.x; d[1] = dv.y; d[2] = dv.z; d[3] = dv.w;
    } else {
#pragma unroll
        for (int i = 0; i < 4; i++) {
            s[i] = ei32[2 * (e + i)];
            d[i] = ei32[2 * (E_EDGES + e + i)];
        }
    }
#pragma unroll
    for (int i = 0; i < 4; i++) {
        int pos = atomicAdd(&g_cur[d[i]], 1);
        float nrm = g_dinv[s[i]] * g_dinv[d[i]];
        g_edge[pos] = make_int2(s[i], __float_as_int(nrm));
    }
}

// ---------------- GEMM1: xw1 = x @ W1 via tf32 mma.sync, half2 epilogue ----
__device__ __forceinline__ uint32_t f2tf32(float f) {
    uint32_t u;
    asm("cvt.rna.tf32.f32 %0, %1;" : "=r"(u) : "f"(f));
    return u;
}

__device__ __forceinline__ void mma_tf32(float* c, const uint32_t* a,
                                         uint32_t b0, uint32_t b1) {
    asm volatile(
        "mma.sync.aligned.m16n8k8.row.col.f32.tf32.tf32.f32 "
        "{%0,%1,%2,%3}, {%4,%5,%6,%7}, {%8,%9}, {%0,%1,%2,%3};"
        : "+f"(c[0]), "+f"(c[1]), "+f"(c[2]), "+f"(c[3])
        : "r"(a[0]), "r"(a[1]), "r"(a[2]), "r"(a[3]), "r"(b0), "r"(b1));
}

#define G1_KT 32

__global__ void k_gemm1(const float* __restrict__ x, const float* __restrict__ W1) {
    __shared__ uint32_t xs[128][36];
    __shared__ uint32_t ws[G1_KT][68];
    int tid = threadIdx.x;
    int wid = tid >> 5;
    int lane = tid & 31;
    int g = lane >> 2;
    int tcol = lane & 3;
    int rb = blockIdx.x * 128;
    int R = wid * 16;

    float c[8][4];
#pragma unroll
    for (int j = 0; j < 8; j++)
#pragma unroll
        for (int i = 0; i < 4; i++) c[j][i] = 0.0f;

    for (int kc = 0; kc < C_IN; kc += G1_KT) {
#pragma unroll
        for (int it = 0; it < 4; it++) {
            int i = tid + 256 * it;
            int row = i >> 3;
            int k4 = (i & 7) << 2;
            int grow = rb + row;
            float4 v = make_float4(0.f, 0.f, 0.f, 0.f);
            if (grow < N_NODES)
                v = *(const float4*)(x + (long)grow * C_IN + kc + k4);
            xs[row][k4 + 0] = f2tf32(v.x);
            xs[row][k4 + 1] = f2tf32(v.y);
            xs[row][k4 + 2] = f2tf32(v.z);
            xs[row][k4 + 3] = f2tf32(v.w);
        }
#pragma unroll
        for (int it = 0; it < 2; it++) {
            int i = tid + 256 * it;
            int wk = i >> 4;
            int wc = (i & 15) << 2;
            float4 v = *(const float4*)(W1 + (kc + wk) * C1 + wc);
            ws[wk][wc + 0] = f2tf32(v.x);
            ws[wk][wc + 1] = f2tf32(v.y);
            ws[wk][wc + 2] = f2tf32(v.z);
            ws[wk][wc + 3] = f2tf32(v.w);
        }
        __syncthreads();

#pragma unroll
        for (int kk = 0; kk < 4; kk++) {
            uint32_t a[4];
            a[0] = xs[R + g][kk * 8 + tcol];
            a[1] = xs[R + g + 8][kk * 8 + tcol];
            a[2] = xs[R + g][kk * 8 + tcol + 4];
            a[3] = xs[R + g + 8][kk * 8 + tcol + 4];
#pragma unroll
            for (int j = 0; j < 8; j++) {
                uint32_t b0 = ws[kk * 8 + tcol][j * 8 + g];
                uint32_t b1 = ws[kk * 8 + tcol + 4][j * 8 + g];
                mma_tf32(c[j], a, b0, b1);
            }
        }
        __syncthreads();
    }

    int row0 = rb + R + g;
    int row1 = row0 + 8;
#pragma unroll
    for (int j = 0; j < 8; j++) {
        int h2col = (j * 8 + 2 * tcol) >> 1;
        if (row0 < N_NODES)
            g_xw1h[(long)row0 * 32 + h2col] = __floats2half2_rn(c[j][0], c[j][1]);
        if (row1 < N_NODES)
            g_xw1h[(long)row1 * 32 + h2col] = __floats2half2_rn(c[j][2], c[j][3]);
    }
}

// --------- layer-1 aggregation (+relu): warp per node, half2 gather --------
__global__ void k_agg1(const float* __restrict__ b1) {
    int w = (blockIdx.x * blockDim.x + threadIdx.x) >> 5;
    int lane = threadIdx.x & 31;
    if (w >= N_NODES) return;
    float dv = g_dinv[w];
    float sl = dv * dv;
    float2 xv = __half22float2(g_xw1h[(long)w * 32 + lane]);
    float2 bv = *(const float2*)(b1 + 2 * lane);
    float a0 = xv.x * sl + bv.x;
    float a1 = xv.y * sl + bv.y;
    int j = g_row[w];
    int end = j + g_degi[w];

    for (; j + 8 <= end; j += 8) {
        int2 e[8];
#pragma unroll
        for (int i = 0; i < 8; i++) e[i] = g_edge[j + i];
        float2 v[8];
#pragma unroll
        for (int i = 0; i < 8; i++)
            v[i] = __half22float2(g_xw1h[(long)e[i].x * 32 + lane]);
#pragma unroll
        for (int i = 0; i < 8; i++) {
            float n = __int_as_float(e[i].y);
            a0 += v[i].x * n;
            a1 += v[i].y * n;
        }
    }
    for (; j < end; j++) {
        int2 e = g_edge[j];
        float n = __int_as_float(e.y);
        float2 v = __half22float2(g_xw1h[(long)e.x * 32 + lane]);
        a0 += v.x * n;
        a1 += v.y * n;
    }
    float2 o;
    o.x = fmaxf(a0, 0.0f);
    o.y = fmaxf(a1, 0.0f);
    *(float2*)(g_out1 + (long)w * C1 + 2 * lane) = o;
}

// ------- GEMM2: xw2 = out1 @ W2 (out1 already relu'd), half2 output --------
__global__ void k_gemm2(const float* __restrict__ W2) {
    __shared__ float xs[64][68];
    __shared__ float ws[64 * 40];
    int t = threadIdx.x;
    int rb = blockIdx.x * 64;
    int r = t >> 2, q = t & 3;

    for (int i = t; i < 64 * 40; i += 256) ws[i] = W2[i];
#pragma unroll
    for (int it = 0; it < 4; it++) {
        int i = t + 256 * it;
        int rr = i >> 4, cc = (i & 15) << 2;
        int row = rb + rr;
        float4 v = make_float4(0.f, 0.f, 0.f, 0.f);
        if (row < N_NODES)
            v = *(const float4*)(g_out1 + (long)row * C1 + cc);
        *(float4*)(&xs[rr][cc]) = v;
    }
    __syncthreads();

    float acc[10];
#pragma unroll
    for (int j = 0; j < 10; j++) acc[j] = 0.0f;
#pragma unroll
    for (int k = 0; k < 64; k++) {
        float xv = xs[r][k];
#pragma unroll
        for (int j = 0; j < 10; j++)
            acc[j] += xv * ws[k * 40 + q * 10 + j];
    }
    int row = rb + r;
    if (row < N_NODES) {
        __half2* o = g_xw2h + (long)row * 20 + q * 5;
#pragma unroll
        for (int j = 0; j < 5; j++)
            o[j] = __floats2half2_rn(acc[2 * j], acc[2 * j + 1]);
    }
}

// ---- layer-2 aggregation + fused log_softmax: warp per node, half2 --------
// lanes 0..19 each own classes {2*lane, 2*lane+1}
__global__ void k_agg2_lsm(const float* __restrict__ b2, float* __restrict__ out) {
    int w = (blockIdx.x * blockDim.x + threadIdx.x) >> 5;
    int lane = threadIdx.x & 31;
    if (w >= N_NODES) return;
    bool act = (lane < 20);
    float dv = g_dinv[w];
    float sl = dv * dv;
    float a0 = 0.0f, a1 = 0.0f;
    if (act) {
        float2 xv = __half22float2(g_xw2h[(long)w * 20 + lane]);
        float2 bv = *(const float2*)(b2 + 2 * lane);
        a0 = xv.x * sl + bv.x;
        a1 = xv.y * sl + bv.y;
    }
    int j = g_row[w];
    int end = j + g_degi[w];

    for (; j + 8 <= end; j += 8) {
        int2 e[8];
#pragma unroll
        for (int i = 0; i < 8; i++) e[i] = g_edge[j + i];
        if (act) {
            float2 v[8];
#pragma unroll
            for (int i = 0; i < 8; i++)
                v[i] = __half22float2(g_xw2h[(long)e[i].x * 20 + lane]);
#pragma unroll
            for (int i = 0; i < 8; i++) {
                float n = __int_as_float(e[i].y);
                a0 += v[i].x * n;
                a1 += v[i].y * n;
            }
        }
    }
    for (; j < end; j++) {
        int2 e = g_edge[j];
        if (act) {
            float n = __int_as_float(e.y);
            float2 v = __half22float2(g_xw2h[(long)e.x * 20 + lane]);
            a0 += v.x * n;
            a1 += v.y * n;
        }
    }

    // log_softmax over 40 values (lanes 0..19 hold 2 each)
    float m = act ? fmaxf(a0, a1) : -INFINITY;
#pragma unroll
    for (int off = 16; off > 0; off >>= 1)
        m = fmaxf(m, __shfl_xor_sync(0xFFFFFFFFu, m, off));
    float s = act ? (expf(a0 - m) + expf(a1 - m)) : 0.0f;
#pragma unroll
    for (int off = 16; off > 0; off >>= 1)
        s += __shfl_xor_sync(0xFFFFFFFFu, s, off);
    float lse = m + logf(s);
    if (act) {
        float2 o = make_float2(a0 - lse, a1 - lse);
        *(float2*)(out + (long)w * C2 + 2 * lane) = o;
    }
}

// ---------------- launch: fork CSR build alongside GEMM1 --------------------
extern "C" void kernel_launch(void* const* d_in, const int* in_sizes, int n_in,
                              void* d_out, int out_size) {
    const float* x   = (const float*)d_in[0];
    const int*   ei  = (const int*)d_in[1];
    const float* W1  = (const float*)d_in[2];
    const float* b1  = (const float*)d_in[3];
    const float* W2  = (const float*)d_in[4];
    const float* b2  = (const float*)d_in[5];
    float* out = (float*)d_out;

    const int TB = 256;

    static cudaStream_t s_csr = nullptr;
    static cudaEvent_t ev_fork = nullptr, ev_join = nullptr;
    if (s_csr == nullptr) {
        cudaStreamCreateWithFlags(&s_csr, cudaStreamNonBlocking);
        cudaEventCreateWithFlags(&ev_fork, cudaEventDisableTiming);
        cudaEventCreateWithFlags(&ev_join, cudaEventDisableTiming);
    }

    cudaEventRecord(ev_fork, 0);
    cudaStreamWaitEvent(s_csr, ev_fork, 0);

    k_zero_detect<<<(N_NODES + TB - 1) / TB, TB, 0, s_csr>>>(ei);
    k_deg_count<<<(E_EDGES / 4 + TB - 1) / TB, TB, 0, s_csr>>>(ei);
    k_scan1_dinv<<<NBLK, SCAN_B, 0, s_csr>>>();
    k_scan23<<<(N_NODES + 255) / 256, 256, 0, s_csr>>>();
    k_fill<<<(E_EDGES / 4 + TB - 1) / TB, TB, 0, s_csr>>>(ei);
    cudaEventRecord(ev_join, s_csr);

    k_gemm1<<<(N_NODES + 127) / 128, 256>>>(x, W1);

    cudaStreamWaitEvent(0, ev_join, 0);

    k_agg1<<<(N_NODES * 32 + TB - 1) / TB, TB>>>(b1);
    k_gemm2<<<(N_NODES + 63) / 64, 256>>>(W2);
    k_agg2_lsm<<<(N_NODES * 32 + TB - 1) / TB, TB>>>(b2, out);
}

// round 15
// speedup vs baseline: 1.2358x; 1.0906x over previous
#include <cuda_runtime.h>
#include <cuda_fp16.h>
#include <stdint.h>
#include <math.h>

#define N_NODES 100000
#define E_EDGES 3200000
#define C_IN 256
#define C1 64
#define C2 40
#define SCAN_B 1024
#define NBLK ((N_NODES + SCAN_B - 1) / SCAN_B)   // 98

// ---------------- scratch (device globals; allocation-free) ----------------
__device__ __align__(16) float g_dinv[N_NODES];
__device__ __align__(16) int   g_degi[N_NODES];    // zeroed by agg2 each call
__device__ __align__(16) int   g_row[N_NODES];
__device__ __align__(16) int   g_rowtmp[N_NODES];
__device__ __align__(16) int   g_cur[N_NODES];
__device__ __align__(16) int   g_bsum[NBLK];
__device__ __align__(16) int   g_esrc[E_EDGES];    // CSR: src ids (4B/edge)
__device__ __align__(16) __half2 g_xw1h[(N_NODES + 128) * 32];  // dinv*x@W1
__device__ __align__(16) float g_out1[N_NODES * C1];     // relu'd aggregate
__device__ __align__(16) __half2 g_xw2h[N_NODES * 20 + 64];  // dinv*out1@W2
__device__ int g_is64;

// ---------------- dtype detection ------------------------------------------
__global__ void k_detect(const int* __restrict__ ei32) {
    if (threadIdx.x == 0) {
        int all0 = 1;
        for (int k = 0; k < 64; k++)
            if (ei32[2 * k + 1] != 0) { all0 = 0; break; }
        g_is64 = all0;
    }
}

// ---------------- CSR build (4 edges per thread) ----------------
__global__ void k_deg_count(const int* __restrict__ ei32) {
    int e4 = blockIdx.x * blockDim.x + threadIdx.x;
    int e = e4 * 4;
    if (e >= E_EDGES) return;
    if (!g_is64) {
        int4 d = *(const int4*)(ei32 + E_EDGES + e);
        atomicAdd(&g_degi[d.x], 1);
        atomicAdd(&g_degi[d.y], 1);
        atomicAdd(&g_degi[d.z], 1);
        atomicAdd(&g_degi[d.w], 1);
    } else {
#pragma unroll
        for (int i = 0; i < 4; i++)
            atomicAdd(&g_degi[ei32[2 * (E_EDGES + e + i)]], 1);
    }
}

__global__ void k_scan1_dinv() {
    __shared__ int sh[SCAN_B];
    int i = blockIdx.x * SCAN_B + threadIdx.x;
    int v = (i < N_NODES) ? g_degi[i] : 0;
    if (i < N_NODES) g_dinv[i] = rsqrtf((float)(v + 1));     // +1 self loop
    sh[threadIdx.x] = v;
    __syncthreads();
    for (int off = 1; off < SCAN_B; off <<= 1) {
        int t = (threadIdx.x >= off) ? sh[threadIdx.x - off] : 0;
        __syncthreads();
        sh[threadIdx.x] += t;
        __syncthreads();
    }
    if (i < N_NODES) g_rowtmp[i] = sh[threadIdx.x];
    if (threadIdx.x == SCAN_B - 1) g_bsum[blockIdx.x] = sh[SCAN_B - 1];
}

// scan2+scan3 merged
__global__ void k_scan23() {
    __shared__ int sh[256];
    int t = threadIdx.x;
    int myblk = blockIdx.x >> 2;
    sh[t] = (t < myblk) ? g_bsum[t] : 0;
    __syncthreads();
#pragma unroll
    for (int off = 128; off > 0; off >>= 1) {
        if (t < off) sh[t] += sh[t + off];
        __syncthreads();
    }
    int boff = sh[0];
    int i = blockIdx.x * 256 + t;
    if (i < N_NODES) {
        int r = g_rowtmp[i] - g_degi[i] + boff;
        g_row[i] = r;
        g_cur[i] = r;
    }
}

__global__ void k_fill(const int* __restrict__ ei32) {
    int e4 = blockIdx.x * blockDim.x + threadIdx.x;
    int e = e4 * 4;
    if (e >= E_EDGES) return;
    int s[4], d[4];
    if (!g_is64) {
        int4 sv = *(const int4*)(ei32 + e);
        int4 dv = *(const int4*)(ei32 + E_EDGES + e);
        s[0] = sv.x; s[1] = sv.y; s[2] = sv.z; s[3] = sv.w;
        d[0] = dv.x; d[1] = dv.y; d[2] = dv.z; d[3] = dv.w;
    } else {
#pragma unroll
        for (int i = 0; i < 4; i++) {
            s[i] = ei32[2 * (e + i)];
            d[i] = ei32[2 * (E_EDGES + e + i)];
        }
    }
#pragma unroll
    for (int i = 0; i < 4; i++) {
        int pos = atomicAdd(&g_cur[d[i]], 1);
        g_esrc[pos] = s[i];
    }
}

// ---------------- GEMM1: y1 = dinv * (x @ W1), tf32 mma, half2 epilogue ----
__device__ __forceinline__ uint32_t f2tf32(float f) {
    uint32_t u;
    asm("cvt.rna.tf32.f32 %0, %1;" : "=r"(u) : "f"(f));
    return u;
}

__device__ __forceinline__ void mma_tf32(float* c, const uint32_t* a,
                                         uint32_t b0, uint32_t b1) {
    asm volatile(
        "mma.sync.aligned.m16n8k8.row.col.f32.tf32.tf32.f32 "
        "{%0,%1,%2,%3}, {%4,%5,%6,%7}, {%8,%9}, {%0,%1,%2,%3};"
        : "+f"(c[0]), "+f"(c[1]), "+f"(c[2]), "+f"(c[3])
        : "r"(a[0]), "r"(a[1]), "r"(a[2]), "r"(a[3]), "r"(b0), "r"(b1));
}

#define G1_KT 32

__global__ void k_gemm1(const float* __restrict__ x, const float* __restrict__ W1) {
    __shared__ uint32_t xs[128][36];
    __shared__ uint32_t ws[G1_KT][68];
    int tid = threadIdx.x;
    int wid = tid >> 5;
    int lane = tid & 31;
    int g = lane >> 2;
    int tcol = lane & 3;
    int rb = blockIdx.x * 128;
    int R = wid * 16;

    float c[8][4];
#pragma unroll
    for (int j = 0; j < 8; j++)
#pragma unroll
        for (int i = 0; i < 4; i++) c[j][i] = 0.0f;

    for (int kc = 0; kc < C_IN; kc += G1_KT) {
#pragma unroll
        for (int it = 0; it < 4; it++) {
            int i = tid + 256 * it;
            int row = i >> 3;
            int k4 = (i & 7) << 2;
            int grow = rb + row;
            float4 v = make_float4(0.f, 0.f, 0.f, 0.f);
            if (grow < N_NODES)
                v = *(const float4*)(x + (long)grow * C_IN + kc + k4);
            xs[row][k4 + 0] = f2tf32(v.x);
            xs[row][k4 + 1] = f2tf32(v.y);
            xs[row][k4 + 2] = f2tf32(v.z);
            xs[row][k4 + 3] = f2tf32(v.w);
        }
#pragma unroll
        for (int it = 0; it < 2; it++) {
            int i = tid + 256 * it;
            int wk = i >> 4;
            int wc = (i & 15) << 2;
            float4 v = *(const float4*)(W1 + (kc + wk) * C1 + wc);
            ws[wk][wc + 0] = f2tf32(v.x);
            ws[wk][wc + 1] = f2tf32(v.y);
            ws[wk][wc + 2] = f2tf32(v.z);
            ws[wk][wc + 3] = f2tf32(v.w);
        }
        __syncthreads();

#pragma unroll
        for (int kk = 0; kk < 4; kk++) {
            uint32_t a[4];
            a[0] = xs[R + g][kk * 8 + tcol];
            a[1] = xs[R + g + 8][kk * 8 + tcol];
            a[2] = xs[R + g][kk * 8 + tcol + 4];
            a[3] = xs[R + g + 8][kk * 8 + tcol + 4];
#pragma unroll
            for (int j = 0; j < 8; j++) {
                uint32_t b0 = ws[kk * 8 + tcol][j * 8 + g];
                uint32_t b1 = ws[kk * 8 + tcol + 4][j * 8 + g];
                mma_tf32(c[j], a, b0, b1);
            }
        }
        __syncthreads();
    }

    int row0 = rb + R + g;
    int row1 = row0 + 8;
    float dv0 = (row0 < N_NODES) ? g_dinv[row0] : 0.0f;
    float dv1 = (row1 < N_NODES) ? g_dinv[row1] : 0.0f;
#pragma unroll
    for (int j = 0; j < 8; j++) {
        int h2col = (j * 8 + 2 * tcol) >> 1;
        if (row0 < N_NODES)
            g_xw1h[(long)row0 * 32 + h2col] =
                __floats2half2_rn(c[j][0] * dv0, c[j][1] * dv0);
        if (row1 < N_NODES)
            g_xw1h[(long)row1 * 32 + h2col] =
                __floats2half2_rn(c[j][2] * dv1, c[j][3] * dv1);
    }
}

// --------- layer-1 aggregation (+relu): warp per node, unweighted sum ------
// out1[d] = relu(dinv[d] * (y1[d] + sum_s y1[s]) + b1)
__global__ void k_agg1(const float* __restrict__ b1) {
    int w = (blockIdx.x * blockDim.x + threadIdx.x) >> 5;
    int lane = threadIdx.x & 31;
    if (w >= N_NODES) return;
    float dv = g_dinv[w];
    float2 xv = __half22float2(g_xw1h[(long)w * 32 + lane]);
    float a0 = xv.x;
    float a1 = xv.y;
    int j = g_row[w];
    int end = j + g_degi[w];

    for (; j + 8 <= end; j += 8) {
        int s[8];
#pragma unroll
        for (int i = 0; i < 8; i++) s[i] = g_esrc[j + i];
        float2 v[8];
#pragma unroll
        for (int i = 0; i < 8; i++)
            v[i] = __half22float2(g_xw1h[(long)s[i] * 32 + lane]);
#pragma unroll
        for (int i = 0; i < 8; i++) {
            a0 += v[i].x;
            a1 += v[i].y;
        }
    }
    for (; j < end; j++) {
        float2 v = __half22float2(g_xw1h[(long)g_esrc[j] * 32 + lane]);
        a0 += v.x;
        a1 += v.y;
    }
    float2 bv = *(const float2*)(b1 + 2 * lane);
    float2 o;
    o.x = fmaxf(a0 * dv + bv.x, 0.0f);
    o.y = fmaxf(a1 * dv + bv.y, 0.0f);
    *(float2*)(g_out1 + (long)w * C1 + 2 * lane) = o;
}

// ------- GEMM2: y2 = dinv * (out1 @ W2), half2 output ----------------------
__global__ void k_gemm2(const float* __restrict__ W2) {
    __shared__ float xs[64][68];
    __shared__ float ws[64 * 40];
    int t = threadIdx.x;
    int rb = blockIdx.x * 64;
    int r = t >> 2, q = t & 3;

    for (int i = t; i < 64 * 40; i += 256) ws[i] = W2[i];
#pragma unroll
    for (int it = 0; it < 4; it++) {
        int i = t + 256 * it;
        int rr = i >> 4, cc = (i & 15) << 2;
        int row = rb + rr;
        float4 v = make_float4(0.f, 0.f, 0.f, 0.f);
        if (row < N_NODES)
            v = *(const float4*)(g_out1 + (long)row * C1 + cc);
        *(float4*)(&xs[rr][cc]) = v;
    }
    __syncthreads();

    float acc[10];
#pragma unroll
    for (int j = 0; j < 10; j++) acc[j] = 0.0f;
#pragma unroll
    for (int k = 0; k < 64; k++) {
        float xv = xs[r][k];
#pragma unroll
        for (int j = 0; j < 10; j++)
            acc[j] += xv * ws[k * 40 + q * 10 + j];
    }
    int row = rb + r;
    if (row < N_NODES) {
        float dv = g_dinv[row];
        __half2* o = g_xw2h + (long)row * 20 + q * 5;
#pragma unroll
        for (int j = 0; j < 5; j++)
            o[j] = __floats2half2_rn(acc[2 * j] * dv, acc[2 * j + 1] * dv);
    }
}

// ---- layer-2 aggregation + fused log_softmax: warp per node ---------------
// logits[d] = dinv[d] * (y2[d] + sum_s y2[s]) + b2
__global__ void k_agg2_lsm(const float* __restrict__ b2, float* __restrict__ out) {
    int w = (blockIdx.x * blockDim.x + threadIdx.x) >> 5;
    int lane = threadIdx.x & 31;
    if (w >= N_NODES) return;
    bool act = (lane < 20);
    float dv = g_dinv[w];
    float a0 = 0.0f, a1 = 0.0f;
    if (act) {
        float2 xv = __half22float2(g_xw2h[(long)w * 20 + lane]);
        a0 = xv.x;
        a1 = xv.y;
    }
    int j = g_row[w];
    int deg = g_degi[w];
    int end = j + deg;

    for (; j + 8 <= end; j += 8) {
        int s[8];
#pragma unroll
        for (int i = 0; i < 8; i++) s[i] = g_esrc[j + i];
        if (act) {
            float2 v[8];
#pragma unroll
            for (int i = 0; i < 8; i++)
                v[i] = __half22float2(g_xw2h[(long)s[i] * 20 + lane]);
#pragma unroll
            for (int i = 0; i < 8; i++) {
                a0 += v[i].x;
                a1 += v[i].y;
            }
        }
    }
    for (; j < end; j++) {
        int s = g_esrc[j];
        if (act) {
            float2 v = __half22float2(g_xw2h[(long)s * 20 + lane]);
            a0 += v.x;
            a1 += v.y;
        }
    }

    if (act) {
        float2 bv = *(const float2*)(b2 + 2 * lane);
        a0 = a0 * dv + bv.x;
        a1 = a1 * dv + bv.y;
    }

    // log_softmax over 40 values (lanes 0..19 hold 2 each)
    float m = act ? fmaxf(a0, a1) : -INFINITY;
#pragma unroll
    for (int off = 16; off > 0; off >>= 1)
        m = fmaxf(m, __shfl_xor_sync(0xFFFFFFFFu, m, off));
    float s = act ? (expf(a0 - m) + expf(a1 - m)) : 0.0f;
#pragma unroll
    for (int off = 16; off > 0; off >>= 1)
        s += __shfl_xor_sync(0xFFFFFFFFu, s, off);
    float lse = m + logf(s);
    if (act) {
        float2 o = make_float2(a0 - lse, a1 - lse);
        *(float2*)(out + (long)w * C2 + 2 * lane) = o;
    }
    // restore invariant: g_degi zeroed for the next call (deterministic)
    if (lane == 0) g_degi[w] = 0;
}

// ---------------- launch: fork CSR build alongside GEMM1 --------------------
extern "C" void kernel_launch(void* const* d_in, const int* in_sizes, int n_in,
                              void* d_out, int out_size) {
    const float* x   = (const float*)d_in[0];
    const int*   ei  = (const int*)d_in[1];
    const float* W1  = (const float*)d_in[2];
    const float* b1  = (const float*)d_in[3];
    const float* W2  = (const float*)d_in[4];
    const float* b2  = (const float*)d_in[5];
    float* out = (float*)d_out;

    const int TB = 256;

    static cudaStream_t s_csr = nullptr;
    static cudaEvent_t ev_fork = nullptr, ev_dinv = nullptr, ev_join = nullptr;
    if (s_csr == nullptr) {
        cudaStreamCreateWithFlags(&s_csr, cudaStreamNonBlocking);
        cudaEventCreateWithFlags(&ev_fork, cudaEventDisableTiming);
        cudaEventCreateWithFlags(&ev_dinv, cudaEventDisableTiming);
        cudaEventCreateWithFlags(&ev_join, cudaEventDisableTiming);
    }

    cudaEventRecord(ev_fork, 0);
    cudaStreamWaitEvent(s_csr, ev_fork, 0);

    k_detect<<<1, 32, 0, s_csr>>>(ei);
    k_deg_count<<<(E_EDGES / 4 + TB - 1) / TB, TB, 0, s_csr>>>(ei);
    k_scan1_dinv<<<NBLK, SCAN_B, 0, s_csr>>>();
    cudaEventRecord(ev_dinv, s_csr);
    k_scan23<<<(N_NODES + 255) / 256, 256, 0, s_csr>>>();
    k_fill<<<(E_EDGES / 4 + TB - 1) / TB, TB, 0, s_csr>>>(ei);
    cudaEventRecord(ev_join, s_csr);

    cudaStreamWaitEvent(0, ev_dinv, 0);
    k_gemm1<<<(N_NODES + 127) / 128, 256>>>(x, W1);

    cudaStreamWaitEvent(0, ev_join, 0);
    k_agg1<<<(N_NODES * 32 + TB - 1) / TB, TB>>>(b1);
    k_gemm2<<<(N_NODES + 63) / 64, 256>>>(W2);
    k_agg2_lsm<<<(N_NODES * 32 + TB - 1) / TB, TB>>>(b2, out);
}